// round 1
// baseline (speedup 1.0000x reference)
#include <cuda_runtime.h>
#include <cstdint>

#define T_STEPS 1000
#define BATCH   64
#define NIN     512
#define NOUT    128
#define LRATE   1.0e-3f
#define DECAY   0.9f

#define NCTA 128
#define NTHR 256

// ---------------- persistent device state (scratch; no allocations) -------
__device__ __align__(16) float g_W[NOUT * NIN];        // working weights
__device__ __align__(16) float g_bias[NOUT];           // working bias
__device__ __align__(16) float g_E[NOUT * BATCH];      // exp(u), [o][b]
__device__ __align__(16) float g_part[BATCH * 32];     // per-(b, o-chunk-half) exp partial sums
__device__ __align__(16) float g_psp[2][BATCH * NIN];  // double-buffered synaptic trace
__device__ unsigned g_count;                            // barrier arrival counter
__device__ volatile unsigned g_epoch;                   // barrier epoch (monotonic)

// ---------------- grid-wide barrier (all NCTA CTAs co-resident) ----------
__device__ __forceinline__ void grid_barrier(unsigned& my_epoch) {
    __syncthreads();
    if (threadIdx.x == 0) {
        unsigned target = ++my_epoch;
        __threadfence();
        unsigned prev = atomicAdd(&g_count, 1u);
        if (prev == NCTA - 1u) {
            g_count = 0u;
            __threadfence();
            g_epoch = target;
        } else {
            while (g_epoch != target) { }
        }
        __threadfence();
    }
    __syncthreads();
}

__global__ void __launch_bounds__(NTHR, 1)
bstdp_kernel(const float* __restrict__ spikes,
             const float* __restrict__ weight,
             const float* __restrict__ bias_in,
             float* __restrict__ out,
             int write_u)
{
    __shared__ float sm[8448];  // 33 KB, unioned across phases

    const int tid  = threadIdx.x;
    const int cta  = blockIdx.x;
    const int w_id = tid >> 5;
    const int lane = tid & 31;

    unsigned my_epoch = 0;
    if (tid == 0) my_epoch = g_epoch;   // quiescent read; continues prior launch's count

    // ---------------- init: copy W/bias, psp[0] = spikes[0] --------------
    {
        // W: 65536 floats = 16384 float4; 128 per CTA
        if (tid < 128)
            ((float4*)g_W)[cta * 128 + tid] =
                ((const float4*)weight)[cta * 128 + tid];
        if (cta == 0 && tid < NOUT) g_bias[tid] = bias_in[tid];
        // psp[0]: 32768 floats = 8192 float4 spread over 32768 threads
        int idx = cta * NTHR + tid;
        if (idx < 8192)
            ((float4*)g_psp[0])[idx] = ((const float4*)spikes)[idx];
    }

    // membrane potential lives in owner-lane registers for the whole run
    float u_reg[16];
#pragma unroll
    for (int i = 0; i < 16; i++) u_reg[i] = 0.0f;

    grid_barrier(my_epoch);

    // ---- phase-A decomposition: 16 o-chunks(8) x 8 b-chunks(8) ----------
    const int ocA  = cta >> 3;
    const int bcA  = cta & 7;
    const int blkA = w_id >> 1;          // 0..3 : (bb, ob)
    const int bbA  = blkA >> 1;
    const int obA  = blkA & 1;
    const int ksA  = ((w_id & 1) << 5) | lane;   // 0..63 K-split

    float* psp_sA  = sm;          // [8][512]
    float* w_sA    = sm + 4096;   // [8][512]
    float* bias_sA = sm + 8192;   // [8]
    float* red_sA  = sm + 8200;   // [4][16]

    // ---- phase-C decomposition: 16 o-chunks(8) x 8 i-chunks(64) ---------
    const int occ = cta >> 3;
    const int icc = cta & 7;
    float* psp_sC = sm;           // [64][68]  (padded rows, conflict-free)
    float* zo_s   = sm + 4352;    // [8][64]
    float* part_s = sm + 4864;    // [64][32]
    float* rden_s = sm + 6912;    // [64]
    float* pm_s   = sm + 6976;    // [8]

    const int blkC = tid >> 3;    // 0..31
    const int ksC  = tid & 7;     // b-split
    const int jbC  = blkC >> 4;   // 0..1  (4 j's)
    const int ibC  = blkC & 15;   // 0..15 (4 i's)

    for (int t = 0; t < T_STEPS; ++t) {
        const int p = t & 1;

        // ================= PHASE A: GEMM1 + u + exp ======================
        {
            const float4* psrc = (const float4*)(g_psp[p] + bcA * 8 * NIN);
            const float4* wsrc = (const float4*)(g_W + ocA * 8 * NIN);
            float4* pdst = (float4*)psp_sA;
            float4* wdst = (float4*)w_sA;
#pragma unroll
            for (int r = 0; r < 4; r++) {
                int i = tid + r * 256;
                pdst[i] = psrc[i];
                wdst[i] = wsrc[i];
            }
            if (tid < 8) bias_sA[tid] = g_bias[ocA * 8 + tid];
            __syncthreads();

            float acc[16];
#pragma unroll
            for (int i = 0; i < 16; i++) acc[i] = 0.0f;

            const float* pr = psp_sA + (bbA * 4) * NIN;
            const float* wr = w_sA + (obA * 4) * NIN;
#pragma unroll
            for (int j = 0; j < 8; j++) {
                int k = ksA + (j << 6);
                float p0 = pr[k];
                float p1 = pr[k + NIN];
                float p2 = pr[k + 2 * NIN];
                float p3 = pr[k + 3 * NIN];
                float q0 = wr[k];
                float q1 = wr[k + NIN];
                float q2 = wr[k + 2 * NIN];
                float q3 = wr[k + 3 * NIN];
                acc[0]  += p0 * q0; acc[1]  += p0 * q1; acc[2]  += p0 * q2; acc[3]  += p0 * q3;
                acc[4]  += p1 * q0; acc[5]  += p1 * q1; acc[6]  += p1 * q2; acc[7]  += p1 * q3;
                acc[8]  += p2 * q0; acc[9]  += p2 * q1; acc[10] += p2 * q2; acc[11] += p2 * q3;
                acc[12] += p3 * q0; acc[13] += p3 * q1; acc[14] += p3 * q2; acc[15] += p3 * q3;
            }
            // reduce over 32 lanes (half of 64-way K-split)
#pragma unroll
            for (int s = 16; s > 0; s >>= 1) {
#pragma unroll
                for (int i = 0; i < 16; i++)
                    acc[i] += __shfl_xor_sync(0xffffffffu, acc[i], s);
            }
            // combine the warp pair of each block via smem
            if ((w_id & 1) && lane == 0) {
#pragma unroll
                for (int i = 0; i < 16; i++) red_sA[blkA * 16 + i] = acc[i];
            }
            __syncthreads();
            if (!(w_id & 1) && lane == 0) {
#pragma unroll
                for (int i = 0; i < 16; i++) acc[i] += red_sA[blkA * 16 + i];
#pragma unroll
                for (int r = 0; r < 4; r++) {
                    int b = bcA * 8 + bbA * 4 + r;
                    float esum = 0.0f;
#pragma unroll
                    for (int c = 0; c < 4; c++) {
                        int o = ocA * 8 + obA * 4 + c;
                        float z = acc[r * 4 + c] + bias_sA[obA * 4 + c];
                        float u = DECAY * u_reg[r * 4 + c] + z;
                        u_reg[r * 4 + c] = u;
                        float e = __expf(u);       // shift-free softmax numerator
                        g_E[o * BATCH + b] = e;
                        esum += e;
                    }
                    g_part[b * 32 + ocA * 2 + obA] = esum;   // deterministic partials
                }
            }
        }
        grid_barrier(my_epoch);

        // ============ PHASE C: z_out, GEMM2, STDP update, psp ============
        {
            // stage psp[:, i-slice] into padded smem tile
#pragma unroll
            for (int r = 0; r < 4; r++) {
                int idx = tid + r * 256;            // 0..1023
                int b = idx >> 4, i4 = idx & 15;
                float4 v = *(const float4*)(g_psp[p] + b * NIN + icc * 64 + i4 * 4);
                *(float4*)(psp_sC + b * 68 + i4 * 4) = v;
            }
            // stage the partial-sum table
#pragma unroll
            for (int r = 0; r < 2; r++) {
                int idx = tid + r * 256;
                ((float4*)part_s)[idx] = ((const float4*)g_part)[idx];
            }
            __syncthreads();
            if (tid < 64) {
                float s = 0.0f;
#pragma unroll
                for (int q = 0; q < 32; q++) s += part_s[tid * 32 + q];
                rden_s[tid] = 1.0f / s;
            }
            __syncthreads();
            // z_out for this o-slice (all b)
#pragma unroll
            for (int r = 0; r < 2; r++) {
                int h = tid + r * 256;              // 0..511
                int j = h >> 6, b = h & 63;
                zo_s[h] = g_E[(occ * 8 + j) * BATCH + b] * rden_s[b];
            }
            __syncthreads();
            if (tid < 8) {
                float s = 0.0f;
#pragma unroll
                for (int b = 0; b < 64; b++) s += zo_s[tid * 64 + b];
                pm_s[tid] = s * (1.0f / BATCH);
            }
            // emit z_out_stack[t] (each CTA writes its 8b x 8o patch)
            if (tid < 64) {
                int b = icc * 8 + (tid >> 3), j = tid & 7;
                out[(size_t)t * (BATCH * NOUT) + b * NOUT + occ * 8 + j] =
                    zo_s[j * 64 + b];
            }
            __syncthreads();

            // GEMM2: pp[j][i] = sum_b zo[j][b] * psp[b][i]
            float acc2[16];
#pragma unroll
            for (int i = 0; i < 16; i++) acc2[i] = 0.0f;
#pragma unroll
            for (int m = 0; m < 8; m++) {
                int b = ksC + (m << 3);
                float4 pv = *(const float4*)(psp_sC + b * 68 + (ibC << 2));
                float z0 = zo_s[(jbC * 4 + 0) * 64 + b];
                float z1 = zo_s[(jbC * 4 + 1) * 64 + b];
                float z2 = zo_s[(jbC * 4 + 2) * 64 + b];
                float z3 = zo_s[(jbC * 4 + 3) * 64 + b];
                acc2[0]  += z0 * pv.x; acc2[1]  += z0 * pv.y; acc2[2]  += z0 * pv.z; acc2[3]  += z0 * pv.w;
                acc2[4]  += z1 * pv.x; acc2[5]  += z1 * pv.y; acc2[6]  += z1 * pv.z; acc2[7]  += z1 * pv.w;
                acc2[8]  += z2 * pv.x; acc2[9]  += z2 * pv.y; acc2[10] += z2 * pv.z; acc2[11] += z2 * pv.w;
                acc2[12] += z3 * pv.x; acc2[13] += z3 * pv.y; acc2[14] += z3 * pv.z; acc2[15] += z3 * pv.w;
            }
#pragma unroll
            for (int s = 4; s > 0; s >>= 1) {
#pragma unroll
                for (int i = 0; i < 16; i++)
                    acc2[i] += __shfl_xor_sync(0xffffffffu, acc2[i], s);
            }
            if (ksC == 0) {
                // fused Nessler STDP update on this CTA's private W patch
#pragma unroll
                for (int jj = 0; jj < 4; jj++) {
                    int o = occ * 8 + jbC * 4 + jj;
                    float4* wp = (float4*)(g_W + o * NIN + icc * 64 + (ibC << 2));
                    float4 w = *wp;
                    float pmv = pm_s[jbC * 4 + jj];
                    w.x += LRATE * (__expf(-w.x) * (acc2[jj * 4 + 0] * (1.0f / BATCH)) - pmv);
                    w.y += LRATE * (__expf(-w.y) * (acc2[jj * 4 + 1] * (1.0f / BATCH)) - pmv);
                    w.z += LRATE * (__expf(-w.z) * (acc2[jj * 4 + 2] * (1.0f / BATCH)) - pmv);
                    w.w += LRATE * (__expf(-w.w) * (acc2[jj * 4 + 3] * (1.0f / BATCH)) - pmv);
                    *wp = w;
                }
            }
            // bias update (one CTA per o-chunk)
            if (icc == 0 && tid < 8) {
                float bb = g_bias[occ * 8 + tid];
                g_bias[occ * 8 + tid] = bb + LRATE * (__expf(-bb) - 1.0f) * pm_s[tid];
            }
            // advance synaptic trace into the other buffer (oc==0 CTAs)
            if (occ == 0 && t + 1 < T_STEPS) {
                const float* sp = spikes + (size_t)(t + 1) * (BATCH * NIN);
#pragma unroll
                for (int r = 0; r < 16; r++) {
                    int e = icc * 4096 + r * 256 + tid;
                    g_psp[p ^ 1][e] = DECAY * g_psp[p][e] + sp[e];
                }
            }
        }
        grid_barrier(my_epoch);
    }

    // ---------------- final membrane potential u_final -------------------
    if (write_u) {
        if (!(w_id & 1) && lane == 0) {
#pragma unroll
            for (int r = 0; r < 4; r++) {
#pragma unroll
                for (int c = 0; c < 4; c++) {
                    int b = bcA * 8 + bbA * 4 + r;
                    int o = ocA * 8 + obA * 4 + c;
                    out[(size_t)T_STEPS * BATCH * NOUT + b * NOUT + o] =
                        u_reg[r * 4 + c];
                }
            }
        }
    }
}

extern "C" void kernel_launch(void* const* d_in, const int* in_sizes, int n_in,
                              void* d_out, int out_size) {
    const float* spikes = nullptr;
    const float* weight = nullptr;
    const float* bias   = nullptr;
    for (int i = 0; i < n_in; i++) {
        if (in_sizes[i] == T_STEPS * BATCH * NIN)      spikes = (const float*)d_in[i];
        else if (in_sizes[i] == NOUT * NIN)            weight = (const float*)d_in[i];
        else if (in_sizes[i] == NOUT)                  bias   = (const float*)d_in[i];
    }
    int write_u = (out_size >= T_STEPS * BATCH * NOUT + BATCH * NOUT) ? 1 : 0;
    bstdp_kernel<<<NCTA, NTHR>>>(spikes, weight, bias, (float*)d_out, write_u);
}

// round 2
// speedup vs baseline: 1.7187x; 1.7187x over previous
#include <cuda_runtime.h>
#include <cstdint>

#define T_STEPS 1000
#define BATCH   64
#define NIN     512
#define NOUT    128
#define LRATE   1.0e-3f
#define DECAY   0.9f

#define NCTA 128
#define NTHR 256

// ---------------- persistent device state (scratch; no allocations) -------
__device__ __align__(16) float g_W[NOUT * NIN];        // working weights
__device__ __align__(16) float g_EW[NOUT * NIN];       // exp(-W), maintained incrementally
__device__ __align__(16) float g_bias[NOUT];           // working bias
__device__ __align__(16) float g_E[NOUT * BATCH];      // exp(u), [o][b]
__device__ __align__(16) float g_part[BATCH * 16];     // per-(b, o-chunk) exp partial sums
__device__ __align__(16) float g_psp[2][BATCH * NIN];  // double-buffered synaptic trace
__device__ unsigned g_count;                            // barrier arrival counter
__device__ unsigned g_epoch;                            // barrier epoch (monotonic)

// ---------------- grid-wide barrier (acq/rel, gpu scope) ------------------
__device__ __forceinline__ void grid_barrier(unsigned& my_epoch) {
    __syncthreads();
    if (threadIdx.x == 0) {
        unsigned target = ++my_epoch;
        unsigned prev;
        asm volatile("atom.acq_rel.gpu.add.u32 %0, [%1], 1;"
                     : "=r"(prev) : "l"(&g_count) : "memory");
        if (prev == NCTA - 1u) {
            asm volatile("st.relaxed.gpu.u32 [%0], 0;" :: "l"(&g_count) : "memory");
            asm volatile("st.release.gpu.u32 [%0], %1;" :: "l"(&g_epoch), "r"(target) : "memory");
        } else {
            unsigned e;
            do {
                asm volatile("ld.acquire.gpu.u32 %0, [%1];" : "=r"(e) : "l"(&g_epoch) : "memory");
            } while (e != target);
        }
    }
    __syncthreads();
}

__global__ void __launch_bounds__(NTHR, 1)
bstdp_kernel(const float* __restrict__ spikes,
             const float* __restrict__ weight,
             const float* __restrict__ bias_in,
             float* __restrict__ out,
             int write_u)
{
    __shared__ float sm[8448];   // unioned across phases (~33 KB)
    __shared__ float u_sm[64];   // persistent membrane tile [8b][8o]

    const int tid  = threadIdx.x;
    const int cta  = blockIdx.x;
    const int w_id = tid >> 5;
    const int lane = tid & 31;

    unsigned my_epoch = 0;
    if (tid == 0) my_epoch = g_epoch;   // quiescent read; continues prior launch's count

    // ---------------- init: copy W/EW/bias, psp[0] = spikes[0] ------------
    if (tid < 128) {
        float4 w = ((const float4*)weight)[cta * 128 + tid];
        ((float4*)g_W)[cta * 128 + tid] = w;
        float4 e;
        e.x = __expf(-w.x); e.y = __expf(-w.y);
        e.z = __expf(-w.z); e.w = __expf(-w.w);
        ((float4*)g_EW)[cta * 128 + tid] = e;
    }
    if (cta == 0 && tid < NOUT) g_bias[tid] = bias_in[tid];
    {
        int idx = cta * NTHR + tid;
        if (idx < 8192)
            ((float4*)g_psp[0])[idx] = ((const float4*)spikes)[idx];
    }
    if (tid < 64) u_sm[tid] = 0.0f;

    grid_barrier(my_epoch);

    // ---- phase-A decomposition: 16 o-chunks(8) x 8 b-chunks(8) ----------
    const int ocA  = cta >> 3;
    const int bcA  = cta & 7;
    const int blkA = w_id >> 1;          // 0..3 : (bb, ob)
    const int bbA  = blkA >> 1;
    const int obA  = blkA & 1;
    const int ksA  = ((w_id & 1) << 5) | lane;   // 0..63 K-split

    float* psp_sA  = sm;          // [8][512]
    float* w_sA    = sm + 4096;   // [8][512]
    float* bias_sA = sm + 8192;   // [8]
    float* red_sA  = sm + 8200;   // [4][32]
    float* z_sA    = sm + 8328;   // [8][8]

    // ---- phase-C decomposition: 16 o-chunks(8) x 8 i-chunks(64) ---------
    const int occ = cta >> 3;
    const int icc = cta & 7;
    float* psp_sC = sm;           // [64][68]  (padded rows, conflict-free)
    float* zo_s   = sm + 4352;    // [8][64]
    float* rden_s = sm + 4864;    // [64]
    float* pm_s   = sm + 4928;    // [8]

    const int blkC = tid >> 3;    // 0..31
    const int ksC  = tid & 7;     // b-split
    const int jbC  = blkC >> 4;   // 0..1  (4 j's)
    const int ibC  = blkC & 15;   // 0..15 (4 i's)

    for (int t = 0; t < T_STEPS; ++t) {
        const int p = t & 1;

        // ================= PHASE A: GEMM1 + u + exp ======================
        {
            const float4* psrc = (const float4*)(g_psp[p] + bcA * 8 * NIN);
            const float4* wsrc = (const float4*)(g_W + ocA * 8 * NIN);
            float4* pdst = (float4*)psp_sA;
            float4* wdst = (float4*)w_sA;
#pragma unroll
            for (int r = 0; r < 4; r++) {
                int i = tid + r * 256;
                pdst[i] = psrc[i];
                wdst[i] = wsrc[i];
            }
            if (tid < 8) bias_sA[tid] = g_bias[ocA * 8 + tid];
            __syncthreads();

            float acc[16];
#pragma unroll
            for (int i = 0; i < 16; i++) acc[i] = 0.0f;

            const float* pr = psp_sA + (bbA * 4) * NIN;
            const float* wr = w_sA + (obA * 4) * NIN;
#pragma unroll
            for (int j = 0; j < 8; j++) {
                int k = ksA + (j << 6);
                float p0 = pr[k];
                float p1 = pr[k + NIN];
                float p2 = pr[k + 2 * NIN];
                float p3 = pr[k + 3 * NIN];
                float q0 = wr[k];
                float q1 = wr[k + NIN];
                float q2 = wr[k + 2 * NIN];
                float q3 = wr[k + 3 * NIN];
                acc[0]  += p0 * q0; acc[1]  += p0 * q1; acc[2]  += p0 * q2; acc[3]  += p0 * q3;
                acc[4]  += p1 * q0; acc[5]  += p1 * q1; acc[6]  += p1 * q2; acc[7]  += p1 * q3;
                acc[8]  += p2 * q0; acc[9]  += p2 * q1; acc[10] += p2 * q2; acc[11] += p2 * q3;
                acc[12] += p3 * q0; acc[13] += p3 * q1; acc[14] += p3 * q2; acc[15] += p3 * q3;
            }
            // value-splitting reduction: 16 outputs over 32 lanes, 16 SHFL
            {
                bool up16 = (lane & 16) != 0;
#pragma unroll
                for (int i = 0; i < 8; i++) {
                    float send = up16 ? acc[i] : acc[i + 8];
                    float keep = up16 ? acc[i + 8] : acc[i];
                    acc[i] = keep + __shfl_xor_sync(0xffffffffu, send, 16);
                }
                bool up8 = (lane & 8) != 0;
#pragma unroll
                for (int i = 0; i < 4; i++) {
                    float send = up8 ? acc[i] : acc[i + 4];
                    float keep = up8 ? acc[i + 4] : acc[i];
                    acc[i] = keep + __shfl_xor_sync(0xffffffffu, send, 8);
                }
                bool up4 = (lane & 4) != 0;
#pragma unroll
                for (int i = 0; i < 2; i++) {
                    float send = up4 ? acc[i] : acc[i + 2];
                    float keep = up4 ? acc[i + 2] : acc[i];
                    acc[i] = keep + __shfl_xor_sync(0xffffffffu, send, 4);
                }
                {
                    bool up2 = (lane & 2) != 0;
                    float send = up2 ? acc[0] : acc[1];
                    float keep = up2 ? acc[1] : acc[0];
                    acc[0] = keep + __shfl_xor_sync(0xffffffffu, send, 2);
                }
                acc[0] += __shfl_xor_sync(0xffffffffu, acc[0], 1);
            }
            // combine warp pairs (K-split halves) via smem
            if (w_id & 1) red_sA[blkA * 32 + lane] = acc[0];
            __syncthreads();
            if (!(w_id & 1)) {
                acc[0] += red_sA[blkA * 32 + lane];
                if (!(lane & 1)) {
                    int oidx = (lane >> 1) & 15;     // r*4+c
                    int r = oidx >> 2, c = oidx & 3;
                    z_sA[(bbA * 4 + r) * 8 + obA * 4 + c] = acc[0];
                }
            }
            __syncthreads();
            // u update + exp, fully parallel over the 64 outputs
            if (tid < 64) {
                int bl = tid >> 3, ol = tid & 7;
                float z = z_sA[bl * 8 + ol] + bias_sA[ol];
                float u = DECAY * u_sm[tid] + z;
                u_sm[tid] = u;
                float e = __expf(u);          // shift-free softmax numerator
                int b = bcA * 8 + bl;
                int o = ocA * 8 + ol;
                g_E[o * BATCH + b] = e;
                e += __shfl_xor_sync(0xffffffffu, e, 1);
                e += __shfl_xor_sync(0xffffffffu, e, 2);
                e += __shfl_xor_sync(0xffffffffu, e, 4);
                if (ol == 0) g_part[b * 16 + ocA] = e;
            }
        }
        grid_barrier(my_epoch);

        // ============ PHASE C: z_out, GEMM2, STDP update, psp ============
        {
            // prefetch psp-advance operands (hide DRAM latency of spikes)
            float4 spk = make_float4(0.f, 0.f, 0.f, 0.f);
            float4 pold = make_float4(0.f, 0.f, 0.f, 0.f);
            const int adv = cta * 64 + tid;
            if (tid < 64) {
                pold = ((const float4*)g_psp[p])[adv];
                if (t + 1 < T_STEPS)
                    spk = ((const float4*)(spikes + (size_t)(t + 1) * (BATCH * NIN)))[adv];
            }

            // stage psp[:, i-slice] into padded smem tile
#pragma unroll
            for (int r = 0; r < 4; r++) {
                int idx = tid + r * 256;            // 0..1023
                int b = idx >> 4, i4 = idx & 15;
                float4 v = *(const float4*)(g_psp[p] + b * NIN + icc * 64 + i4 * 4);
                *(float4*)(psp_sC + b * 68 + i4 * 4) = v;
            }
            // softmax denominators: 4 threads per b
            {
                float4 pv = ((const float4*)g_part)[tid];   // [b=tid>>2][4q..]
                float s = pv.x + pv.y + pv.z + pv.w;
                s += __shfl_xor_sync(0xffffffffu, s, 1);
                s += __shfl_xor_sync(0xffffffffu, s, 2);
                if ((tid & 3) == 0) rden_s[tid >> 2] = 1.0f / s;
            }
            __syncthreads();
            // z_out for this o-slice (all b)
#pragma unroll
            for (int r = 0; r < 2; r++) {
                int h = tid + r * 256;              // 0..511
                int j = h >> 6, b = h & 63;
                zo_s[h] = g_E[(occ * 8 + j) * BATCH + b] * rden_s[b];
            }
            __syncthreads();
            // post_mean: one warp per output row
            {
                float s = zo_s[w_id * 64 + lane] + zo_s[w_id * 64 + 32 + lane];
#pragma unroll
                for (int m = 16; m > 0; m >>= 1)
                    s += __shfl_xor_sync(0xffffffffu, s, m);
                if (lane == 0) pm_s[w_id] = s * (1.0f / BATCH);
            }
            // emit z_out_stack[t] (each CTA writes its 8b x 8o patch)
            if (tid < 64) {
                int b = icc * 8 + (tid >> 3), j = tid & 7;
                out[(size_t)t * (BATCH * NOUT) + b * NOUT + occ * 8 + j] =
                    zo_s[j * 64 + b];
            }

            // GEMM2: pp[j][i] = sum_b zo[j][b] * psp[b][i]
            float acc2[16];
#pragma unroll
            for (int i = 0; i < 16; i++) acc2[i] = 0.0f;
#pragma unroll
            for (int m = 0; m < 8; m++) {
                int b = ksC + (m << 3);
                float4 pv = *(const float4*)(psp_sC + b * 68 + (ibC << 2));
                float z0 = zo_s[(jbC * 4 + 0) * 64 + b];
                float z1 = zo_s[(jbC * 4 + 1) * 64 + b];
                float z2 = zo_s[(jbC * 4 + 2) * 64 + b];
                float z3 = zo_s[(jbC * 4 + 3) * 64 + b];
                acc2[0]  += z0 * pv.x; acc2[1]  += z0 * pv.y; acc2[2]  += z0 * pv.z; acc2[3]  += z0 * pv.w;
                acc2[4]  += z1 * pv.x; acc2[5]  += z1 * pv.y; acc2[6]  += z1 * pv.z; acc2[7]  += z1 * pv.w;
                acc2[8]  += z2 * pv.x; acc2[9]  += z2 * pv.y; acc2[10] += z2 * pv.z; acc2[11] += z2 * pv.w;
                acc2[12] += z3 * pv.x; acc2[13] += z3 * pv.y; acc2[14] += z3 * pv.z; acc2[15] += z3 * pv.w;
            }
#pragma unroll
            for (int s = 4; s > 0; s >>= 1) {
#pragma unroll
                for (int i = 0; i < 16; i++)
                    acc2[i] += __shfl_xor_sync(0xffffffffu, acc2[i], s);
            }
            __syncthreads();   // pm_s visible to updaters
            if (ksC == 0) {
                // fused Nessler STDP update; EW tracks exp(-W) via 2nd-order poly
                const float inv = 1.0f / BATCH;
#pragma unroll
                for (int jj = 0; jj < 4; jj++) {
                    int o = occ * 8 + jbC * 4 + jj;
                    int wi = o * NIN + icc * 64 + (ibC << 2);
                    float4 w  = *(float4*)(g_W + wi);
                    float4 ew = *(float4*)(g_EW + wi);
                    float pmv = pm_s[jbC * 4 + jj];
                    float d0 = LRATE * (ew.x * (acc2[jj * 4 + 0] * inv) - pmv);
                    float d1 = LRATE * (ew.y * (acc2[jj * 4 + 1] * inv) - pmv);
                    float d2 = LRATE * (ew.z * (acc2[jj * 4 + 2] * inv) - pmv);
                    float d3 = LRATE * (ew.w * (acc2[jj * 4 + 3] * inv) - pmv);
                    w.x += d0; w.y += d1; w.z += d2; w.w += d3;
                    ew.x *= (1.0f - d0 + 0.5f * d0 * d0);
                    ew.y *= (1.0f - d1 + 0.5f * d1 * d1);
                    ew.z *= (1.0f - d2 + 0.5f * d2 * d2);
                    ew.w *= (1.0f - d3 + 0.5f * d3 * d3);
                    *(float4*)(g_W + wi)  = w;
                    *(float4*)(g_EW + wi) = ew;
                }
            }
            // bias update (one CTA per o-chunk)
            if (icc == 0 && tid < 8) {
                float bb = g_bias[occ * 8 + tid];
                g_bias[occ * 8 + tid] = bb + LRATE * (__expf(-bb) - 1.0f) * pm_s[tid];
            }
            // psp advance, distributed over all CTAs (1 float4/thread slice)
            if (tid < 64 && t + 1 < T_STEPS) {
                float4 pn;
                pn.x = DECAY * pold.x + spk.x;
                pn.y = DECAY * pold.y + spk.y;
                pn.z = DECAY * pold.z + spk.z;
                pn.w = DECAY * pold.w + spk.w;
                ((float4*)g_psp[p ^ 1])[adv] = pn;
            }
        }
        grid_barrier(my_epoch);
    }

    // ---------------- final membrane potential u_final -------------------
    if (write_u && tid < 64) {
        int b = bcA * 8 + (tid >> 3);
        int o = ocA * 8 + (tid & 7);
        out[(size_t)T_STEPS * BATCH * NOUT + b * NOUT + o] = u_sm[tid];
    }
}

extern "C" void kernel_launch(void* const* d_in, const int* in_sizes, int n_in,
                              void* d_out, int out_size) {
    const float* spikes = nullptr;
    const float* weight = nullptr;
    const float* bias   = nullptr;
    for (int i = 0; i < n_in; i++) {
        if (in_sizes[i] == T_STEPS * BATCH * NIN)      spikes = (const float*)d_in[i];
        else if (in_sizes[i] == NOUT * NIN)            weight = (const float*)d_in[i];
        else if (in_sizes[i] == NOUT)                  bias   = (const float*)d_in[i];
    }
    int write_u = (out_size >= T_STEPS * BATCH * NOUT + BATCH * NOUT) ? 1 : 0;
    bstdp_kernel<<<NCTA, NTHR>>>(spikes, weight, bias, (float*)d_out, write_u);
}